// round 1
// baseline (speedup 1.0000x reference)
#include <cuda_runtime.h>

#define NV 50257
#define NE 256
#define NC 48
#define NB 64
#define NT 1024

#define ROWS 128
#define PAD  260   // padded K-stride (floats): 16B-aligned rows, stride%32==4 -> conflict-free LDS

static __device__ float g_partial[NB];

// ---------- packed f32x2 helpers (Blackwell sm_100a) ----------
__device__ __forceinline__ unsigned long long ffma2(unsigned long long a, unsigned long long b,
                                                    unsigned long long c) {
    unsigned long long d;
    asm("fma.rn.f32x2 %0, %1, %2, %3;" : "=l"(d) : "l"(a), "l"(b), "l"(c));
    return d;
}
__device__ __forceinline__ unsigned long long fadd2(unsigned long long a, unsigned long long b) {
    unsigned long long d;
    asm("add.rn.f32x2 %0, %1, %2;" : "=l"(d) : "l"(a), "l"(b));
    return d;
}
__device__ __forceinline__ float2 unpack2(unsigned long long a) {
    float2 f;
    asm("mov.b64 {%0, %1}, %2;" : "=f"(f.x), "=f"(f.y) : "l"(a));
    return f;
}
__device__ __forceinline__ unsigned long long pack2(float x, float y) {
    unsigned long long d;
    asm("mov.b64 %0, {%1, %2};" : "=l"(d) : "f"(x), "f"(y));
    return d;
}

// ============================================================================
// Kernel 1: logits[b,t,c] = emb_table[x[b,t]] . fc_w[c] + fc_b[c]
// Tiled smem GEMM, 128 gathered rows x 48 cols x K=256, packed f32x2 FMA.
// Thread tile: 4 rows (ty + 32m) x 6 cols (tx + 8n), 256 threads.
// ============================================================================
__global__ __launch_bounds__(256) void gemm_kernel(
    const int* __restrict__ x, const float* __restrict__ emb,
    const float* __restrict__ fcw, const float* __restrict__ fcb,
    float* __restrict__ out)
{
    extern __shared__ float sm[];
    float* fcw_s = sm;                       // NC * PAD
    float* emb_s = sm + NC * PAD;            // ROWS * PAD
    int*   x_s   = (int*)(sm + NC * PAD + ROWS * PAD);

    const int tid = threadIdx.x;
    const int rowBase = blockIdx.x * ROWS;
    if (tid < ROWS) x_s[tid] = x[rowBase + tid];

    // stage fc_w (48x256) into padded smem
    for (int i = tid; i < NC * (NE / 4); i += 256) {
        int c = i >> 6, k4 = i & 63;
        float4 v = ((const float4*)fcw)[i];
        *(float4*)&fcw_s[c * PAD + k4 * 4] = v;
    }
    __syncthreads();
    // gather 128 embedding rows into padded smem
    for (int i = tid; i < ROWS * (NE / 4); i += 256) {
        int r = i >> 6, k4 = i & 63;
        float4 v = ((const float4*)(emb + (size_t)x_s[r] * NE))[k4];
        *(float4*)&emb_s[r * PAD + k4 * 4] = v;
    }
    __syncthreads();

    const int tx = tid & 7;   // col group
    const int ty = tid >> 3;  // row group (0..31)

    unsigned long long acc[4][6];
    #pragma unroll
    for (int m = 0; m < 4; m++)
        #pragma unroll
        for (int n = 0; n < 6; n++) acc[m][n] = 0ull;

    #pragma unroll 4
    for (int k2 = 0; k2 < NE / 2; k2++) {
        unsigned long long a2[4], w2[6];
        #pragma unroll
        for (int m = 0; m < 4; m++)
            a2[m] = *(const unsigned long long*)&emb_s[(ty + 32 * m) * PAD + 2 * k2];
        #pragma unroll
        for (int n = 0; n < 6; n++)
            w2[n] = *(const unsigned long long*)&fcw_s[(tx + 8 * n) * PAD + 2 * k2];
        #pragma unroll
        for (int m = 0; m < 4; m++)
            #pragma unroll
            for (int n = 0; n < 6; n++)
                acc[m][n] = ffma2(a2[m], w2[n], acc[m][n]);
    }

    #pragma unroll
    for (int m = 0; m < 4; m++) {
        int r = rowBase + ty + 32 * m;
        #pragma unroll
        for (int n = 0; n < 6; n++) {
            int c = tx + 8 * n;
            float2 p = unpack2(acc[m][n]);
            out[(size_t)r * NC + c] = p.x + p.y + __ldg(&fcb[c]);
        }
    }
}

// ============================================================================
// Kernel 2: CRF. One block per batch (64 threads / 2 warps, 48 active states).
// Linear-space forward scan: a_{t+1}[c] = (sum_i a_t[i] * exp(trans[i][c])/64)
//                                          * exp(logits[t+1,c]),
// renormalized every 128 steps; logZ reassembled from the accumulated scale.
// E columns live in registers as 24 f32x2 pairs -> 24 FFMA2 per step.
// Emissions register-prefetched 4 steps ahead (L2-resident logits).
// ============================================================================
__global__ __launch_bounds__(64) void crf_kernel(
    const float* __restrict__ logits,   // == d_out
    const int* __restrict__ labels,
    const float* __restrict__ start_trans,
    const float* __restrict__ end_trans,
    const float* __restrict__ trans)
{
    __shared__ __align__(16) float a_sh[2][64];
    __shared__ float red[64];

    const int b   = blockIdx.x;
    const int tid = threadIdx.x;
    const float* lg  = logits + (size_t)b * NT * NC;
    const int*   lab = labels + b * NT;

    // ---- numerator (parallel over t, fixed-order reduce) ----
    float acc = 0.f;
    for (int t = tid; t < NT; t += 64) {
        int lt = lab[t];
        acc += lg[t * NC + lt];
        if (t + 1 < NT) {
            int lt1 = lab[t + 1];
            acc += trans[lt * NC + lt1];
        }
    }
    if (tid == 0)  acc += start_trans[lab[0]];
    if (tid == 63) acc += end_trans[lab[NT - 1]];
    red[tid] = acc;
    __syncthreads();

    float num = 0.f;
    if (tid == 0) {
        #pragma unroll
        for (int i = 0; i < 64; i++) num += red[i];
    }

    // ---- per-thread state setup ----
    const int  c      = tid;
    const bool active = (c < NC);

    unsigned long long Ec2[24];
    float a_cur = 0.f;
    if (active) {
        #pragma unroll
        for (int j = 0; j < 24; j++) {
            float e0 = __expf(trans[(2 * j)     * NC + c]) * 0.015625f;  // /64
            float e1 = __expf(trans[(2 * j + 1) * NC + c]) * 0.015625f;
            Ec2[j] = pack2(e0, e1);
        }
        a_cur = __expf(start_trans[c] + lg[c]);   // alpha_0 = start + logits[:,0]
        a_sh[0][c] = a_cur;
    }

    float logscale = 0.f;

    // prefetch emissions for t = 1..4
    float eb[4];
    if (active) {
        #pragma unroll
        for (int jj = 0; jj < 4; jj++) eb[jj] = lg[(1 + jj) * NC + c];
    }
    __syncthreads();

    int p = 0;
    for (int tb = 1; tb < NT; tb += 4) {
        float en[4] = {0.f, 0.f, 0.f, 0.f};
        if (active) {
            #pragma unroll
            for (int jj = 0; jj < 4; jj++) {
                int tt = tb + 4 + jj;
                if (tt < NT) en[jj] = lg[tt * NC + c];
            }
        }
        #pragma unroll
        for (int jj = 0; jj < 4; jj++) {
            int t = tb + jj;
            if (t >= NT) break;                    // uniform across block
            if (active) {
                unsigned long long s0 = 0ull, s1 = 0ull;
                #pragma unroll
                for (int j = 0; j < 12; j++) {
                    ulonglong2 u = *(const ulonglong2*)&a_sh[p][4 * j];
                    s0 = ffma2(u.x, Ec2[2 * j],     s0);
                    s1 = ffma2(u.y, Ec2[2 * j + 1], s1);
                }
                float2 sp = unpack2(fadd2(s0, s1));
                float s = sp.x + sp.y;
                float anew = s * __expf(eb[jj]);
                if ((t & 127) == 0) {              // renormalize every 128 steps
                    float r = a_sh[p][0];
                    anew = __fdividef(anew, r);
                    if (c == 0) logscale += __logf(r);
                }
                a_sh[p ^ 1][c] = anew;
                a_cur = anew;
            }
            __syncthreads();
            p ^= 1;
        }
        if (active) {
            eb[0] = en[0]; eb[1] = en[1]; eb[2] = en[2]; eb[3] = en[3];
        }
    }

    // ---- logZ and per-batch partial ----
    if (active) red[c] = a_cur * __expf(end_trans[c]);
    __syncthreads();
    if (tid == 0) {
        float s = 0.f;
        #pragma unroll
        for (int i = 0; i < NC; i++) s += red[i];
        // compensate: 1023 steps each carried a 1/64 scale -> +1023*ln(64)
        float logz = __logf(s) + logscale + 4254.5374f;
        g_partial[b] = num - logz;
    }
}

// ============================================================================
// Kernel 3: deterministic fixed-order final reduce -> d_out[out_size-1] = -llh
// ============================================================================
__global__ void finish_kernel(float* __restrict__ out, int out_size)
{
    if (threadIdx.x == 0 && blockIdx.x == 0) {
        float s = 0.f;
        #pragma unroll
        for (int i = 0; i < NB; i++) s += g_partial[i];
        out[out_size - 1] = -s;
    }
}

extern "C" void kernel_launch(void* const* d_in, const int* in_sizes, int n_in,
                              void* d_out, int out_size)
{
    const int*   x    = (const int*)  d_in[0];
    const int*   lab  = (const int*)  d_in[1];
    const float* emb  = (const float*)d_in[2];
    const float* fcw  = (const float*)d_in[3];
    const float* fcb  = (const float*)d_in[4];
    const float* st   = (const float*)d_in[5];
    const float* et   = (const float*)d_in[6];
    const float* tr   = (const float*)d_in[7];
    float* out = (float*)d_out;

    const size_t smem = (size_t)(NC * PAD + ROWS * PAD) * sizeof(float) + ROWS * sizeof(int);
    cudaFuncSetAttribute(gemm_kernel, cudaFuncAttributeMaxDynamicSharedMemorySize, (int)smem);

    gemm_kernel<<<(NB * NT) / ROWS, 256, smem>>>(x, emb, fcw, fcb, out);
    crf_kernel<<<NB, 64>>>(out, lab, st, et, tr);
    finish_kernel<<<1, 32>>>(out, out_size);
}

// round 2
// speedup vs baseline: 1.5319x; 1.5319x over previous
#include <cuda_runtime.h>

#define NV 50257
#define NE 256
#define NC 48
#define NB 64
#define NT 1024

#define ROWS 128
#define KT   64
#define PAD2 68   // 68 % 32 == 4 -> conflict-free strided LDS

static __device__ float g_partial[NB];

// ---------- packed f32x2 helpers ----------
__device__ __forceinline__ unsigned long long ffma2(unsigned long long a, unsigned long long b,
                                                    unsigned long long c) {
    unsigned long long d;
    asm("fma.rn.f32x2 %0, %1, %2, %3;" : "=l"(d) : "l"(a), "l"(b), "l"(c));
    return d;
}
__device__ __forceinline__ unsigned long long fadd2(unsigned long long a, unsigned long long b) {
    unsigned long long d;
    asm("add.rn.f32x2 %0, %1, %2;" : "=l"(d) : "l"(a), "l"(b));
    return d;
}
__device__ __forceinline__ float2 unpack2(unsigned long long a) {
    float2 f;
    asm("mov.b64 {%0, %1}, %2;" : "=f"(f.x), "=f"(f.y) : "l"(a));
    return f;
}
__device__ __forceinline__ unsigned long long pack2(float x, float y) {
    unsigned long long d;
    asm("mov.b64 %0, {%1, %2};" : "=l"(d) : "f"(x), "f"(y));
    return d;
}
__device__ __forceinline__ float frcp_fast(float x) {
    float r; asm("rcp.approx.f32 %0, %1;" : "=f"(r) : "f"(x)); return r;
}

// ============================================================================
// Kernel 1: logits = gather(emb)[65536 x 256] @ fc_w^T [48 x 256] + fc_b
// K split into 4 tiles of 64 -> 48.4KB smem/block -> 3 blocks/SM (24 warps).
// Thread tile 4 rows x 6 cols, packed f32x2 FMA.
// ============================================================================
__global__ __launch_bounds__(256, 3) void gemm_kernel(
    const int* __restrict__ x, const float* __restrict__ emb,
    const float* __restrict__ fcw, const float* __restrict__ fcb,
    float* __restrict__ out)
{
    __shared__ float fcw_s[NC * PAD2];
    __shared__ float emb_s[ROWS * PAD2];
    __shared__ int   x_s[ROWS];

    const int tid = threadIdx.x;
    const int rowBase = blockIdx.x * ROWS;
    if (tid < ROWS) x_s[tid] = x[rowBase + tid];
    __syncthreads();

    const int tx = tid & 7;   // col group
    const int ty = tid >> 3;  // row group 0..31

    unsigned long long acc[4][6];
    #pragma unroll
    for (int m = 0; m < 4; m++)
        #pragma unroll
        for (int n = 0; n < 6; n++) acc[m][n] = 0ull;

    for (int kt = 0; kt < 4; kt++) {
        const int k0 = kt * KT;
        // stage fc_w tile: 48 x 64 floats = 768 float4
        for (int i = tid; i < NC * (KT / 4); i += 256) {
            int c = i >> 4, k4 = i & 15;
            float4 v = ((const float4*)(fcw + c * NE + k0))[k4];
            *(float4*)&fcw_s[c * PAD2 + 4 * k4] = v;
        }
        // gather emb tile: 128 x 64 floats = 2048 float4
        for (int i = tid; i < ROWS * (KT / 4); i += 256) {
            int r = i >> 4, k4 = i & 15;
            float4 v = ((const float4*)(emb + (size_t)x_s[r] * NE + k0))[k4];
            *(float4*)&emb_s[r * PAD2 + 4 * k4] = v;
        }
        __syncthreads();

        #pragma unroll 2
        for (int k2 = 0; k2 < KT / 2; k2++) {
            unsigned long long a2[4], w2[6];
            #pragma unroll
            for (int m = 0; m < 4; m++)
                a2[m] = *(const unsigned long long*)&emb_s[(ty + 32 * m) * PAD2 + 2 * k2];
            #pragma unroll
            for (int n = 0; n < 6; n++)
                w2[n] = *(const unsigned long long*)&fcw_s[(tx + 8 * n) * PAD2 + 2 * k2];
            #pragma unroll
            for (int m = 0; m < 4; m++)
                #pragma unroll
                for (int n = 0; n < 6; n++)
                    acc[m][n] = ffma2(a2[m], w2[n], acc[m][n]);
        }
        __syncthreads();
    }

    #pragma unroll
    for (int m = 0; m < 4; m++) {
        int r = rowBase + ty + 32 * m;
        #pragma unroll
        for (int n = 0; n < 6; n++) {
            int c = tx + 8 * n;
            float2 p = unpack2(acc[m][n]);
            out[(size_t)r * NC + c] = p.x + p.y + __ldg(&fcb[c]);
        }
    }
}

// ============================================================================
// Kernel 2: CRF forward scan, one block per chain, 64 threads, BRANCH-FREE
// inner loop (all 64 lanes compute; lanes 48..63 use clamped indices and
// write to unread smem slots). Linear-space with E=exp(trans)/64, branchless
// renorm every 128 steps via rcp.approx + selp.
// ============================================================================
__global__ __launch_bounds__(64) void crf_kernel(
    const float* __restrict__ logits,
    const int* __restrict__ labels,
    const float* __restrict__ start_trans,
    const float* __restrict__ end_trans,
    const float* __restrict__ trans)
{
    __shared__ __align__(16) float a_sh[2][64];
    __shared__ float red[64];

    const int b   = blockIdx.x;
    const int tid = threadIdx.x;
    const float* lg  = logits + (size_t)b * NT * NC;
    const int*   lab = labels + b * NT;

    // ---- numerator (parallel over t, fixed-order reduce) ----
    float acc = 0.f;
    for (int t = tid; t < NT; t += 64) {
        int lt = lab[t];
        acc += lg[t * NC + lt];
        if (t + 1 < NT) acc += trans[lt * NC + lab[t + 1]];
    }
    if (tid == 0)  acc += start_trans[lab[0]];
    if (tid == 63) acc += end_trans[lab[NT - 1]];
    red[tid] = acc;
    __syncthreads();
    float num = 0.f;
    if (tid == 0) {
        #pragma unroll
        for (int i = 0; i < 64; i++) num += red[i];
    }

    // ---- branch-free setup: all 64 lanes compute with clamped state index ----
    const int cc = (tid < NC) ? tid : (NC - 1);

    unsigned long long Ec2[24];
    #pragma unroll
    for (int j = 0; j < 24; j++) {
        float e0 = __expf(trans[(2 * j)     * NC + cc]) * 0.015625f;  // /64
        float e1 = __expf(trans[(2 * j + 1) * NC + cc]) * 0.015625f;
        Ec2[j] = pack2(e0, e1);
    }
    float a_cur = __expf(start_trans[cc] + lg[cc]);
    a_sh[0][tid] = a_cur;

    float logscale = 0.f;

    float eb[4];
    #pragma unroll
    for (int jj = 0; jj < 4; jj++) eb[jj] = lg[(1 + jj) * NC + cc];
    __syncthreads();

    int p = 0;

    // one fully branch-free scan step
    #define CRF_STEP(T, EMIS)                                                  \
    {                                                                          \
        float ex = __expf(EMIS);                                               \
        float r  = a_sh[p][0];                                                 \
        unsigned long long s0 = 0ull, s1 = 0ull, s2 = 0ull, s3 = 0ull;         \
        _Pragma("unroll")                                                      \
        for (int j = 0; j < 12; j += 2) {                                      \
            ulonglong2 u = *(const ulonglong2*)&a_sh[p][4 * j];                \
            ulonglong2 v = *(const ulonglong2*)&a_sh[p][4 * j + 4];            \
            s0 = ffma2(u.x, Ec2[2 * j],     s0);                               \
            s1 = ffma2(u.y, Ec2[2 * j + 1], s1);                               \
            s2 = ffma2(v.x, Ec2[2 * j + 2], s2);                               \
            s3 = ffma2(v.y, Ec2[2 * j + 3], s3);                               \
        }                                                                      \
        float2 sp = unpack2(fadd2(fadd2(s0, s2), fadd2(s1, s3)));              \
        float s = sp.x + sp.y;                                                 \
        bool rn = ((T) & 127) == 0;                                            \
        float sel = rn ? frcp_fast(r) : 1.0f;                                  \
        logscale += rn ? __logf(r) : 0.0f;                                     \
        float anew = s * ex * sel;                                             \
        a_sh[p ^ 1][tid] = anew;                                               \
        a_cur = anew;                                                          \
        __syncthreads();                                                       \
        p ^= 1;                                                                \
    }

    // main loop: t = 1 .. 1020, groups of 4, no interior branches
    for (int tb = 1; tb + 3 < NT; tb += 4) {
        float en[4];
        #pragma unroll
        for (int jj = 0; jj < 4; jj++) {
            int tt = tb + 4 + jj;
            tt = (tt < NT) ? tt : (NT - 1);
            en[jj] = lg[tt * NC + cc];
        }
        CRF_STEP(tb + 0, eb[0]);
        CRF_STEP(tb + 1, eb[1]);
        CRF_STEP(tb + 2, eb[2]);
        CRF_STEP(tb + 3, eb[3]);
        eb[0] = en[0]; eb[1] = en[1]; eb[2] = en[2]; eb[3] = en[3];
    }
    // epilogue: t = 1021, 1022, 1023
    CRF_STEP(NT - 3, eb[0]);
    CRF_STEP(NT - 2, eb[1]);
    CRF_STEP(NT - 1, eb[2]);
    #undef CRF_STEP

    // ---- logZ and per-batch partial ----
    if (tid < NC) red[tid] = a_cur * __expf(end_trans[tid]);
    __syncthreads();
    if (tid == 0) {
        float s = 0.f;
        #pragma unroll
        for (int i = 0; i < NC; i++) s += red[i];
        // 1023 steps each carried a 1/64 scale -> +1023*ln(64)
        float logz = __logf(s) + logscale + 4254.5374f;
        g_partial[b] = num - logz;
    }
}

// ============================================================================
// Kernel 3: deterministic final reduce -> d_out[out_size-1] = -llh
// ============================================================================
__global__ void finish_kernel(float* __restrict__ out, int out_size)
{
    if (threadIdx.x == 0 && blockIdx.x == 0) {
        float s = 0.f;
        #pragma unroll
        for (int i = 0; i < NB; i++) s += g_partial[i];
        out[out_size - 1] = -s;
    }
}

extern "C" void kernel_launch(void* const* d_in, const int* in_sizes, int n_in,
                              void* d_out, int out_size)
{
    const int*   x    = (const int*)  d_in[0];
    const int*   lab  = (const int*)  d_in[1];
    const float* emb  = (const float*)d_in[2];
    const float* fcw  = (const float*)d_in[3];
    const float* fcb  = (const float*)d_in[4];
    const float* st   = (const float*)d_in[5];
    const float* et   = (const float*)d_in[6];
    const float* tr   = (const float*)d_in[7];
    float* out = (float*)d_out;

    gemm_kernel<<<(NB * NT) / ROWS, 256>>>(x, emb, fcw, fcb, out);
    crf_kernel<<<NB, 64>>>(out, lab, st, et, tr);
    finish_kernel<<<1, 32>>>(out, out_size);
}